// round 15
// baseline (speedup 1.0000x reference)
#include <cuda_runtime.h>
#include <float.h>

// Problem constants (from reference)
#define NS   32
#define NH   32
#define KVH  8
#define QPK  4
#define HS   128
#define BS   16
#define MB   128
#define PART 128
#define NPARTS 16                // MB*BS / PART = 2048/128
#define SCALE 0.08838834764831843f   // 1/sqrt(128)

#define QPAD 4
#define LSTRIDE (PART + 4)       // 132 floats: 16B-aligned rows, banks offset by 4
#define NBLK (PART / BS)         // 8 blocks per partition

// Split-K partial scratch (8MB + 64KB) + arrival counters (zero-init)
__device__ float g_pout[(size_t)NS*KVH*QPK*NPARTS*HS];
__device__ float g_pm[NS*KVH*QPK*NPARTS];
__device__ float g_pl[NS*KVH*QPK*NPARTS];
__device__ int   g_cnt[NS*KVH];   // returns to 0 at the end of every launch

// One CTA = (kv_head h, seq n, partition p). 256 threads. Single fused kernel.
// Grid order (h, n, p): all always-active p=0 items launch first; the
// mostly-inactive high-p slots trail, giving a dense work prefix.
// Phase 1: warp w owns cache block w; 16 fully-coalesced LDG.128 per warp,
//          gated off for warps entirely past L (no dead K planes).
// Phase 2: lane = (s-quarter, d-row); block-pair loop breaks past ntok.
// Tail:    last-arriving CTA per (n,h) group combines partials -> out.
__global__ __launch_bounds__(256, 7) void attn_fused(
    const float* __restrict__ q,    const float* __restrict__ knew,
    const float* __restrict__ vnew, const float* __restrict__ kc,
    const float* __restrict__ vc,   const int*   __restrict__ bt,
    const int*   __restrict__ ctx,  float* __restrict__ out)
{
    int h = blockIdx.x, n = blockIdx.y, p = blockIdx.z;
    int L = ctx[n];
    int start = p * PART;
    if (start >= L) return;               // uniform across CTA
    int ntok = min(PART, L - start);
    int np   = (L + PART - 1) / PART;     // active partitions in this group

    __shared__ float s_q[QPK][HS + QPAD];
    __shared__ float s_logits[QPK][LSTRIDE]; // raw logits, then exp values
    __shared__ int   s_bt[NBLK];
    __shared__ float s_m[QPK][8];
    __shared__ float s_mf[QPK];
    __shared__ float s_lred[QPK][8];
    __shared__ int   s_last;

    int tid  = threadIdx.x;
    int lane = tid & 31, w = tid >> 5;

    // Stage Q + this partition's block-table slice into smem
    for (int i = tid; i < QPK * HS; i += 256) {
        int qi = i >> 7, dd = i & (HS - 1);
        s_q[qi][dd] = q[((size_t)n*NH + h*QPK + qi)*HS + dd];
    }
    if (tid < NBLK) s_bt[tid] = bt[n*MB + (start >> 4) + tid];
    __syncthreads();

    // ---- Phase 1: logits; warp w reads block w's K plane coalesced ----
    if (start + w*16 < L) {               // warp-uniform: skip dead K planes
        int blk = s_bt[w];
        const float* base = kc + ((size_t)blk*KVH + h)*(HS*BS);
        int xh = lane & 1;            // which 16B half of the 8-float x-group
        float a0 = 0.f, a1 = 0.f, a2 = 0.f, a3 = 0.f;
#pragma unroll
        for (int d2 = 0; d2 < 16; d2++) {
            // lane l -> token l/2, head dims d2*8 + (l&1)*4 .. +4 (memory order)
            float4 kv = *(const float4*)(base + d2*128 + lane*4);
            float4 q0 = *(const float4*)&s_q[0][d2*8 + xh*4];
            float4 q1 = *(const float4*)&s_q[1][d2*8 + xh*4];
            float4 q2 = *(const float4*)&s_q[2][d2*8 + xh*4];
            float4 q3 = *(const float4*)&s_q[3][d2*8 + xh*4];
            a0 += kv.x*q0.x + kv.y*q0.y + kv.z*q0.z + kv.w*q0.w;
            a1 += kv.x*q1.x + kv.y*q1.y + kv.z*q1.z + kv.w*q1.w;
            a2 += kv.x*q2.x + kv.y*q2.y + kv.z*q2.z + kv.w*q2.w;
            a3 += kv.x*q3.x + kv.y*q3.y + kv.z*q3.z + kv.w*q3.w;
        }
        // merge the lane pair (each pair = one token)
        a0 += __shfl_xor_sync(0xffffffffu, a0, 1);
        a1 += __shfl_xor_sync(0xffffffffu, a1, 1);
        a2 += __shfl_xor_sync(0xffffffffu, a2, 1);
        a3 += __shfl_xor_sync(0xffffffffu, a3, 1);

        int t = start + w*16 + (lane >> 1);
        if (t < L) {
            int ts = t - start;
            if ((lane & 1) == 0) {
                s_logits[0][ts] = a0 * SCALE;
                s_logits[1][ts] = a1 * SCALE;
            } else {
                s_logits[2][ts] = a2 * SCALE;
                s_logits[3][ts] = a3 * SCALE;
            }
        }
    }
    __syncthreads();

    // Override the new token's logit: its K comes from `knew`, not the cache.
    {
        int tn = L - 1;
        if (tn >= start && tn < start + PART) {   // uniform across CTA
            if (w < QPK) {                        // warp w handles head w
                const float4* kp = (const float4*)(knew + ((size_t)n*KVH + h)*HS);
                float4 kv = kp[lane];
                float4 qv = *(const float4*)&s_q[w][lane*4];
                float dot = kv.x*qv.x + kv.y*qv.y + kv.z*qv.z + kv.w*qv.w;
#pragma unroll
                for (int off = 16; off; off >>= 1)
                    dot += __shfl_xor_sync(0xffffffffu, dot, off);
                if (lane == 0) s_logits[w][tn - start] = dot * SCALE;
            }
            __syncthreads();
        }
    }

    // ---- max + exp + sum over the partition (token = tid, first 128 tids) ----
    float lg[QPK], mloc[QPK];
#pragma unroll
    for (int k = 0; k < QPK; k++) {
        lg[k]   = (tid < ntok) ? s_logits[k][tid] : -FLT_MAX;
        mloc[k] = lg[k];
    }
#pragma unroll
    for (int off = 16; off; off >>= 1)
#pragma unroll
        for (int k = 0; k < QPK; k++)
            mloc[k] = fmaxf(mloc[k], __shfl_xor_sync(0xffffffffu, mloc[k], off));
    if (lane == 0)
#pragma unroll
        for (int k = 0; k < QPK; k++) s_m[k][w] = mloc[k];
    __syncthreads();
    if (tid < QPK) {
        float m = s_m[tid][0];
#pragma unroll
        for (int i = 1; i < 8; i++) m = fmaxf(m, s_m[tid][i]);
        s_mf[tid] = m;
    }
    __syncthreads();

    float lsum[QPK];
#pragma unroll
    for (int k = 0; k < QPK; k++) {
        float e = (tid < ntok) ? __expf(lg[k] - s_mf[k]) : 0.f;
        if (tid < PART) s_logits[k][tid] = e;
        lsum[k] = e;
    }
#pragma unroll
    for (int off = 16; off; off >>= 1)
#pragma unroll
        for (int k = 0; k < QPK; k++)
            lsum[k] += __shfl_xor_sync(0xffffffffu, lsum[k], off);
    if (lane == 0)
#pragma unroll
        for (int k = 0; k < QPK; k++) s_lred[k][w] = lsum[k];
    __syncthreads();

    if (tid < QPK) {
        float l = 0.f;
#pragma unroll
        for (int i = 0; i < 8; i++) l += s_lred[tid][i];
        int pid = ((n*KVH + h)*QPK + tid)*NPARTS + p;
        g_pm[pid] = s_mf[tid];
        g_pl[pid] = l;
    }

    // ---- Phase 2: V accumulation; pair loop breaks past live tokens ----
    int s4 = tid & 3;
    int db = tid >> 2;                  // 0..63
    float acc[QPK][2];
#pragma unroll
    for (int k = 0; k < QPK; k++) acc[k][0] = acc[k][1] = 0.f;

#pragma unroll
    for (int b = 0; b < NBLK; b += 2) {
        if (b*16 >= ntok) break;        // weights beyond ntok are zero
        const float* vbA = vc + ((size_t)s_bt[b  ]*KVH + h)*(HS*BS);
        const float* vbB = vc + ((size_t)s_bt[b+1]*KVH + h)*(HS*BS);
        float4 vA0 = *(const float4*)(vbA + db*BS + s4*4);
        float4 vA1 = *(const float4*)(vbA + (db + 64)*BS + s4*4);
        float4 vB0 = *(const float4*)(vbB + db*BS + s4*4);
        float4 vB1 = *(const float4*)(vbB + (db + 64)*BS + s4*4);
#pragma unroll
        for (int k = 0; k < QPK; k++) {
            float4 wA = *(const float4*)&s_logits[k][b*16 + s4*4];
            float4 wB = *(const float4*)&s_logits[k][(b+1)*16 + s4*4];
            acc[k][0] += wA.x*vA0.x + wA.y*vA0.y + wA.z*vA0.z + wA.w*vA0.w;
            acc[k][1] += wA.x*vA1.x + wA.y*vA1.y + wA.z*vA1.z + wA.w*vA1.w;
            acc[k][0] += wB.x*vB0.x + wB.y*vB0.y + wB.z*vB0.z + wB.w*vB0.w;
            acc[k][1] += wB.x*vB1.x + wB.y*vB1.y + wB.z*vB1.z + wB.w*vB1.w;
        }
    }

    // Correct the new token: replace stale cached V with v_new contribution.
    int tl = L - 1;
    if (tl >= start && tl < start + ntok && ((tl & 15) >> 2) == s4) {
        int blk = s_bt[(tl - start) >> 4];
        int s   = tl & 15;
        const float* vbase = vc + ((size_t)blk*KVH + h)*(HS*BS);
        float vst0 = vbase[db*BS + s];
        float vst1 = vbase[(db + 64)*BS + s];
        float vn0  = vnew[((size_t)n*KVH + h)*HS + db];
        float vn1  = vnew[((size_t)n*KVH + h)*HS + db + 64];
        float dd0 = vn0 - vst0, dd1 = vn1 - vst1;
#pragma unroll
        for (int k = 0; k < QPK; k++) {
            float wv = s_logits[k][tl - start];
            acc[k][0] += wv * dd0;
            acc[k][1] += wv * dd1;
        }
    }

    // Combine the 4 s-quarters (lane bits 0..1)
#pragma unroll
    for (int k = 0; k < QPK; k++) {
#pragma unroll
        for (int j = 0; j < 2; j++) {
            acc[k][j] += __shfl_xor_sync(0xffffffffu, acc[k][j], 1);
            acc[k][j] += __shfl_xor_sync(0xffffffffu, acc[k][j], 2);
        }
    }
    if (s4 == 0) {
#pragma unroll
        for (int k = 0; k < QPK; k++) {
            size_t pid = (size_t)((n*KVH + h)*QPK + k)*NPARTS + p;
            g_pout[pid*HS + db]      = acc[k][0];
            g_pout[pid*HS + db + 64] = acc[k][1];
        }
    }

    // ---- Tail: last-arriving CTA of the (n,h) group does the combine ----
    __threadfence();                     // publish this CTA's partials GPU-wide
    __syncthreads();
    if (tid == 0) {
        int v = atomicAdd(&g_cnt[n*KVH + h], 1);
        s_last = (v == np - 1);
    }
    __syncthreads();
    if (!s_last) return;

    if (tid == 0) g_cnt[n*KVH + h] = 0;  // reset counter for the next launch
    __threadfence();                     // acquire other CTAs' published writes

    // 256 threads cover 4 heads x 128 dims (2 dims each)
    int k  = tid >> 6;                   // q-head 0..3
    int dd = tid & 63;                   // dim base 0..63 (also dd+64)
    int gbase = ((n*KVH + h)*QPK + k)*NPARTS;

    float m = -FLT_MAX;
    for (int pp = 0; pp < np; pp++) m = fmaxf(m, g_pm[gbase + pp]);
    float l = 0.f, o0 = 0.f, o1 = 0.f;
    for (int pp = 0; pp < np; pp++) {
        float a = __expf(g_pm[gbase + pp] - m);
        l  += a * g_pl[gbase + pp];
        o0 += a * g_pout[(size_t)(gbase + pp)*HS + dd];
        o1 += a * g_pout[(size_t)(gbase + pp)*HS + dd + 64];
    }
    float inv = 1.f / l;
    out[((size_t)n*NH + h*QPK + k)*HS + dd]      = o0 * inv;
    out[((size_t)n*NH + h*QPK + k)*HS + dd + 64] = o1 * inv;
}

extern "C" void kernel_launch(void* const* d_in, const int* in_sizes, int n_in,
                              void* d_out, int out_size)
{
    const float* q   = (const float*)d_in[0];
    const float* k   = (const float*)d_in[1];
    const float* v   = (const float*)d_in[2];
    const float* kc  = (const float*)d_in[3];
    const float* vc  = (const float*)d_in[4];
    const int*   bt  = (const int*)d_in[5];
    const int*   ctx = (const int*)d_in[6];

    dim3 g1(KVH, NS, NPARTS);   // p slowest: dense active prefix, sparse tail
    attn_fused<<<g1, 256>>>(q, k, v, kc, vc, bt, ctx, (float*)d_out);
}

// round 16
// speedup vs baseline: 1.0360x; 1.0360x over previous
#include <cuda_runtime.h>
#include <float.h>

// Problem constants (from reference)
#define NS   32
#define NH   32
#define KVH  8
#define QPK  4
#define HS   128
#define BS   16
#define MB   128
#define PART 128
#define NPARTS 16                // MB*BS / PART = 2048/128
#define SCALE 0.08838834764831843f   // 1/sqrt(128)

#define QPAD 4
#define LSTRIDE (PART + 4)       // 132 floats: 16B-aligned rows, banks offset by 4
#define NBLK (PART / BS)         // 8 blocks per partition

// Split-K partial scratch (8MB + 64KB) + arrival counters (zero-init)
__device__ float g_pout[(size_t)NS*KVH*QPK*NPARTS*HS];
__device__ float g_pm[NS*KVH*QPK*NPARTS];
__device__ float g_pl[NS*KVH*QPK*NPARTS];
__device__ int   g_cnt[NS*KVH];   // returns to 0 at the end of every launch

// One CTA = (kv_head h, partition p, seq n). 256 threads. Single fused kernel.
// Phase 1: warp w owns cache block w; 16 fully-coalesced LDG.128 per warp,
//          warp-uniform gated so fully-dead K planes are skipped (batching
//          inside the taken path is unaffected).
// Phase 2: lane = (s-quarter, d-row); statically unrolled over all 8 blocks
//          (zero weights absorb dead tokens) -> 16 front-batched LDG.128.
// Tail:    last-arriving CTA per (n,h) group combines partials -> out.
__global__ __launch_bounds__(256, 8) void attn_fused(
    const float* __restrict__ q,    const float* __restrict__ knew,
    const float* __restrict__ vnew, const float* __restrict__ kc,
    const float* __restrict__ vc,   const int*   __restrict__ bt,
    const int*   __restrict__ ctx,  float* __restrict__ out)
{
    int h = blockIdx.x, p = blockIdx.y, n = blockIdx.z;
    int L = ctx[n];
    int start = p * PART;
    if (start >= L) return;               // uniform across CTA
    int ntok = min(PART, L - start);
    int np   = (L + PART - 1) / PART;     // active partitions in this group

    __shared__ float s_q[QPK][HS + QPAD];
    __shared__ float s_logits[QPK][LSTRIDE]; // raw logits, then exp values
    __shared__ int   s_bt[NBLK];
    __shared__ float s_m[QPK][8];
    __shared__ float s_mf[QPK];
    __shared__ float s_lred[QPK][8];
    __shared__ int   s_last;

    int tid  = threadIdx.x;
    int lane = tid & 31, w = tid >> 5;

    // Stage Q + this partition's block-table slice into smem
    for (int i = tid; i < QPK * HS; i += 256) {
        int qi = i >> 7, dd = i & (HS - 1);
        s_q[qi][dd] = q[((size_t)n*NH + h*QPK + qi)*HS + dd];
    }
    if (tid < NBLK) s_bt[tid] = bt[n*MB + (start >> 4) + tid];
    __syncthreads();

    // ---- Phase 1: logits; warp w reads block w's K plane coalesced ----
    if (start + w*16 < L) {               // warp-uniform: skip dead K planes
        int blk = s_bt[w];
        const float* base = kc + ((size_t)blk*KVH + h)*(HS*BS);
        int xh = lane & 1;            // which 16B half of the 8-float x-group
        float a0 = 0.f, a1 = 0.f, a2 = 0.f, a3 = 0.f;
#pragma unroll
        for (int d2 = 0; d2 < 16; d2++) {
            // lane l -> token l/2, head dims d2*8 + (l&1)*4 .. +4 (memory order)
            float4 kv = *(const float4*)(base + d2*128 + lane*4);
            float4 q0 = *(const float4*)&s_q[0][d2*8 + xh*4];
            float4 q1 = *(const float4*)&s_q[1][d2*8 + xh*4];
            float4 q2 = *(const float4*)&s_q[2][d2*8 + xh*4];
            float4 q3 = *(const float4*)&s_q[3][d2*8 + xh*4];
            a0 += kv.x*q0.x + kv.y*q0.y + kv.z*q0.z + kv.w*q0.w;
            a1 += kv.x*q1.x + kv.y*q1.y + kv.z*q1.z + kv.w*q1.w;
            a2 += kv.x*q2.x + kv.y*q2.y + kv.z*q2.z + kv.w*q2.w;
            a3 += kv.x*q3.x + kv.y*q3.y + kv.z*q3.z + kv.w*q3.w;
        }
        // merge the lane pair (each pair = one token)
        a0 += __shfl_xor_sync(0xffffffffu, a0, 1);
        a1 += __shfl_xor_sync(0xffffffffu, a1, 1);
        a2 += __shfl_xor_sync(0xffffffffu, a2, 1);
        a3 += __shfl_xor_sync(0xffffffffu, a3, 1);

        int t = start + w*16 + (lane >> 1);
        if (t < L) {
            int ts = t - start;
            if ((lane & 1) == 0) {
                s_logits[0][ts] = a0 * SCALE;
                s_logits[1][ts] = a1 * SCALE;
            } else {
                s_logits[2][ts] = a2 * SCALE;
                s_logits[3][ts] = a3 * SCALE;
            }
        }
    }
    __syncthreads();

    // Override the new token's logit: its K comes from `knew`, not the cache.
    {
        int tn = L - 1;
        if (tn >= start && tn < start + PART) {   // uniform across CTA
            if (w < QPK) {                        // warp w handles head w
                const float4* kp = (const float4*)(knew + ((size_t)n*KVH + h)*HS);
                float4 kv = kp[lane];
                float4 qv = *(const float4*)&s_q[w][lane*4];
                float dot = kv.x*qv.x + kv.y*qv.y + kv.z*qv.z + kv.w*qv.w;
#pragma unroll
                for (int off = 16; off; off >>= 1)
                    dot += __shfl_xor_sync(0xffffffffu, dot, off);
                if (lane == 0) s_logits[w][tn - start] = dot * SCALE;
            }
            __syncthreads();
        }
    }

    // ---- max + exp + sum over the partition (token = tid, first 128 tids) ----
    float lg[QPK], mloc[QPK];
#pragma unroll
    for (int k = 0; k < QPK; k++) {
        lg[k]   = (tid < ntok) ? s_logits[k][tid] : -FLT_MAX;
        mloc[k] = lg[k];
    }
#pragma unroll
    for (int off = 16; off; off >>= 1)
#pragma unroll
        for (int k = 0; k < QPK; k++)
            mloc[k] = fmaxf(mloc[k], __shfl_xor_sync(0xffffffffu, mloc[k], off));
    if (lane == 0)
#pragma unroll
        for (int k = 0; k < QPK; k++) s_m[k][w] = mloc[k];
    __syncthreads();
    if (tid < QPK) {
        float m = s_m[tid][0];
#pragma unroll
        for (int i = 1; i < 8; i++) m = fmaxf(m, s_m[tid][i]);
        s_mf[tid] = m;
    }
    __syncthreads();

    float lsum[QPK];
#pragma unroll
    for (int k = 0; k < QPK; k++) {
        float e = (tid < ntok) ? __expf(lg[k] - s_mf[k]) : 0.f;
        if (tid < PART) s_logits[k][tid] = e;
        lsum[k] = e;
    }
#pragma unroll
    for (int off = 16; off; off >>= 1)
#pragma unroll
        for (int k = 0; k < QPK; k++)
            lsum[k] += __shfl_xor_sync(0xffffffffu, lsum[k], off);
    if (lane == 0)
#pragma unroll
        for (int k = 0; k < QPK; k++) s_lred[k][w] = lsum[k];
    __syncthreads();

    if (tid < QPK) {
        float l = 0.f;
#pragma unroll
        for (int i = 0; i < 8; i++) l += s_lred[tid][i];
        int pid = ((n*KVH + h)*QPK + tid)*NPARTS + p;
        g_pm[pid] = s_mf[tid];
        g_pl[pid] = l;
    }

    // ---- Phase 2: V accumulation, statically unrolled over all 8 blocks ----
    int s4 = tid & 3;
    int db = tid >> 2;                  // 0..63
    float acc[QPK][2];
#pragma unroll
    for (int k = 0; k < QPK; k++) acc[k][0] = acc[k][1] = 0.f;

#pragma unroll
    for (int b = 0; b < NBLK; b += 2) {
        const float* vbA = vc + ((size_t)s_bt[b  ]*KVH + h)*(HS*BS);
        const float* vbB = vc + ((size_t)s_bt[b+1]*KVH + h)*(HS*BS);
        float4 vA0 = *(const float4*)(vbA + db*BS + s4*4);
        float4 vA1 = *(const float4*)(vbA + (db + 64)*BS + s4*4);
        float4 vB0 = *(const float4*)(vbB + db*BS + s4*4);
        float4 vB1 = *(const float4*)(vbB + (db + 64)*BS + s4*4);
#pragma unroll
        for (int k = 0; k < QPK; k++) {
            float4 wA = *(const float4*)&s_logits[k][b*16 + s4*4];
            float4 wB = *(const float4*)&s_logits[k][(b+1)*16 + s4*4];
            acc[k][0] += wA.x*vA0.x + wA.y*vA0.y + wA.z*vA0.z + wA.w*vA0.w;
            acc[k][1] += wA.x*vA1.x + wA.y*vA1.y + wA.z*vA1.z + wA.w*vA1.w;
            acc[k][0] += wB.x*vB0.x + wB.y*vB0.y + wB.z*vB0.z + wB.w*vB0.w;
            acc[k][1] += wB.x*vB1.x + wB.y*vB1.y + wB.z*vB1.z + wB.w*vB1.w;
        }
    }

    // Correct the new token: replace stale cached V with v_new contribution.
    int tl = L - 1;
    if (tl >= start && tl < start + ntok && ((tl & 15) >> 2) == s4) {
        int blk = s_bt[(tl - start) >> 4];
        int s   = tl & 15;
        const float* vbase = vc + ((size_t)blk*KVH + h)*(HS*BS);
        float vst0 = vbase[db*BS + s];
        float vst1 = vbase[(db + 64)*BS + s];
        float vn0  = vnew[((size_t)n*KVH + h)*HS + db];
        float vn1  = vnew[((size_t)n*KVH + h)*HS + db + 64];
        float dd0 = vn0 - vst0, dd1 = vn1 - vst1;
#pragma unroll
        for (int k = 0; k < QPK; k++) {
            float wv = s_logits[k][tl - start];
            acc[k][0] += wv * dd0;
            acc[k][1] += wv * dd1;
        }
    }

    // Combine the 4 s-quarters (lane bits 0..1)
#pragma unroll
    for (int k = 0; k < QPK; k++) {
#pragma unroll
        for (int j = 0; j < 2; j++) {
            acc[k][j] += __shfl_xor_sync(0xffffffffu, acc[k][j], 1);
            acc[k][j] += __shfl_xor_sync(0xffffffffu, acc[k][j], 2);
        }
    }
    if (s4 == 0) {
#pragma unroll
        for (int k = 0; k < QPK; k++) {
            size_t pid = (size_t)((n*KVH + h)*QPK + k)*NPARTS + p;
            g_pout[pid*HS + db]      = acc[k][0];
            g_pout[pid*HS + db + 64] = acc[k][1];
        }
    }

    // ---- Tail: last-arriving CTA of the (n,h) group does the combine ----
    __threadfence();                     // publish this CTA's partials GPU-wide
    __syncthreads();
    if (tid == 0) {
        int v = atomicAdd(&g_cnt[n*KVH + h], 1);
        s_last = (v == np - 1);
    }
    __syncthreads();
    if (!s_last) return;

    if (tid == 0) g_cnt[n*KVH + h] = 0;  // reset counter for the next launch
    __threadfence();                     // acquire other CTAs' published writes

    // 256 threads cover 4 heads x 128 dims (2 dims each)
    int k  = tid >> 6;                   // q-head 0..3
    int dd = tid & 63;                   // dim base 0..63 (also dd+64)
    int gbase = ((n*KVH + h)*QPK + k)*NPARTS;

    float m = -FLT_MAX;
    for (int pp = 0; pp < np; pp++) m = fmaxf(m, g_pm[gbase + pp]);
    float l = 0.f, o0 = 0.f, o1 = 0.f;
    for (int pp = 0; pp < np; pp++) {
        float a = __expf(g_pm[gbase + pp] - m);
        l  += a * g_pl[gbase + pp];
        o0 += a * g_pout[(size_t)(gbase + pp)*HS + dd];
        o1 += a * g_pout[(size_t)(gbase + pp)*HS + dd + 64];
    }
    float inv = 1.f / l;
    out[((size_t)n*NH + h*QPK + k)*HS + dd]      = o0 * inv;
    out[((size_t)n*NH + h*QPK + k)*HS + dd + 64] = o1 * inv;
}

extern "C" void kernel_launch(void* const* d_in, const int* in_sizes, int n_in,
                              void* d_out, int out_size)
{
    const float* q   = (const float*)d_in[0];
    const float* k   = (const float*)d_in[1];
    const float* v   = (const float*)d_in[2];
    const float* kc  = (const float*)d_in[3];
    const float* vc  = (const float*)d_in[4];
    const int*   bt  = (const int*)d_in[5];
    const int*   ctx = (const int*)d_in[6];

    dim3 g1(KVH, NPARTS, NS);   // R14 grid order restored
    attn_fused<<<g1, 256>>>(q, k, v, kc, vc, bt, ctx, (float*)d_out);
}

// round 17
// speedup vs baseline: 1.0979x; 1.0597x over previous
#include <cuda_runtime.h>
#include <float.h>

// Problem constants (from reference)
#define NS   32
#define NH   32
#define KVH  8
#define QPK  4
#define HS   128
#define BS   16
#define MB   128
#define PART 128
#define NPARTS 16                // MB*BS / PART = 2048/128
#define SCALE 0.08838834764831843f   // 1/sqrt(128)

#define QPAD 4
#define LSTRIDE (PART + 4)       // 132 floats: 16B-aligned rows, banks offset by 4
#define NBLK (PART / BS)         // 8 blocks per partition

// Split-K partial scratch (8MB + 64KB) + arrival counters (zero-init)
__device__ float g_pout[(size_t)NS*KVH*QPK*NPARTS*HS];
__device__ float g_pm[NS*KVH*QPK*NPARTS];
__device__ float g_pl[NS*KVH*QPK*NPARTS];
__device__ int   g_cnt[NS*KVH];   // returns to 0 at the end of every launch

// One CTA = (kv_head h, partition p, seq n). 256 threads. Single fused kernel.
// Phase 1: warp w owns cache block w; 16 fully-coalesced LDG.128 per warp.
// Phase 2: lane = (s-quarter, d-row); statically unrolled over all 8 blocks.
// KV loads use __ldcs (evict-first): zero-reuse data stays out of L2 so the
// scratch round trip (g_pout) remains L2-resident for the reduce tail.
// Tail:    last-arriving CTA per (n,h) group combines partials -> out.
__global__ __launch_bounds__(256, 7) void attn_fused(
    const float* __restrict__ q,    const float* __restrict__ knew,
    const float* __restrict__ vnew, const float* __restrict__ kc,
    const float* __restrict__ vc,   const int*   __restrict__ bt,
    const int*   __restrict__ ctx,  float* __restrict__ out)
{
    int h = blockIdx.x, p = blockIdx.y, n = blockIdx.z;
    int L = ctx[n];
    int start = p * PART;
    if (start >= L) return;               // uniform across CTA
    int ntok = min(PART, L - start);
    int np   = (L + PART - 1) / PART;     // active partitions in this group

    __shared__ float s_q[QPK][HS + QPAD];
    __shared__ float s_logits[QPK][LSTRIDE]; // raw logits, then exp values
    __shared__ int   s_bt[NBLK];
    __shared__ float s_m[QPK][8];
    __shared__ float s_mf[QPK];
    __shared__ float s_lred[QPK][8];
    __shared__ int   s_last;

    int tid  = threadIdx.x;
    int lane = tid & 31, w = tid >> 5;

    // Stage Q + this partition's block-table slice into smem
    for (int i = tid; i < QPK * HS; i += 256) {
        int qi = i >> 7, dd = i & (HS - 1);
        s_q[qi][dd] = q[((size_t)n*NH + h*QPK + qi)*HS + dd];
    }
    if (tid < NBLK) s_bt[tid] = bt[n*MB + (start >> 4) + tid];
    __syncthreads();

    // ---- Phase 1: logits; warp w reads block w's K plane coalesced ----
    {
        int blk = s_bt[w];
        const float* base = kc + ((size_t)blk*KVH + h)*(HS*BS);
        int xh = lane & 1;            // which 16B half of the 8-float x-group
        float a0 = 0.f, a1 = 0.f, a2 = 0.f, a3 = 0.f;
#pragma unroll
        for (int d2 = 0; d2 < 16; d2++) {
            // lane l -> token l/2, head dims d2*8 + (l&1)*4 .. +4 (memory order)
            float4 kv = __ldcs((const float4*)(base + d2*128 + lane*4));
            float4 q0 = *(const float4*)&s_q[0][d2*8 + xh*4];
            float4 q1 = *(const float4*)&s_q[1][d2*8 + xh*4];
            float4 q2 = *(const float4*)&s_q[2][d2*8 + xh*4];
            float4 q3 = *(const float4*)&s_q[3][d2*8 + xh*4];
            a0 += kv.x*q0.x + kv.y*q0.y + kv.z*q0.z + kv.w*q0.w;
            a1 += kv.x*q1.x + kv.y*q1.y + kv.z*q1.z + kv.w*q1.w;
            a2 += kv.x*q2.x + kv.y*q2.y + kv.z*q2.z + kv.w*q2.w;
            a3 += kv.x*q3.x + kv.y*q3.y + kv.z*q3.z + kv.w*q3.w;
        }
        // merge the lane pair (each pair = one token)
        a0 += __shfl_xor_sync(0xffffffffu, a0, 1);
        a1 += __shfl_xor_sync(0xffffffffu, a1, 1);
        a2 += __shfl_xor_sync(0xffffffffu, a2, 1);
        a3 += __shfl_xor_sync(0xffffffffu, a3, 1);

        int t = start + w*16 + (lane >> 1);
        if (t < L) {
            int ts = t - start;
            if ((lane & 1) == 0) {
                s_logits[0][ts] = a0 * SCALE;
                s_logits[1][ts] = a1 * SCALE;
            } else {
                s_logits[2][ts] = a2 * SCALE;
                s_logits[3][ts] = a3 * SCALE;
            }
        }
    }
    __syncthreads();

    // Override the new token's logit: its K comes from `knew`, not the cache.
    {
        int tn = L - 1;
        if (tn >= start && tn < start + PART) {   // uniform across CTA
            if (w < QPK) {                        // warp w handles head w
                const float4* kp = (const float4*)(knew + ((size_t)n*KVH + h)*HS);
                float4 kv = kp[lane];
                float4 qv = *(const float4*)&s_q[w][lane*4];
                float dot = kv.x*qv.x + kv.y*qv.y + kv.z*qv.z + kv.w*qv.w;
#pragma unroll
                for (int off = 16; off; off >>= 1)
                    dot += __shfl_xor_sync(0xffffffffu, dot, off);
                if (lane == 0) s_logits[w][tn - start] = dot * SCALE;
            }
            __syncthreads();
        }
    }

    // ---- max + exp + sum over the partition (token = tid, first 128 tids) ----
    float lg[QPK], mloc[QPK];
#pragma unroll
    for (int k = 0; k < QPK; k++) {
        lg[k]   = (tid < ntok) ? s_logits[k][tid] : -FLT_MAX;
        mloc[k] = lg[k];
    }
#pragma unroll
    for (int off = 16; off; off >>= 1)
#pragma unroll
        for (int k = 0; k < QPK; k++)
            mloc[k] = fmaxf(mloc[k], __shfl_xor_sync(0xffffffffu, mloc[k], off));
    if (lane == 0)
#pragma unroll
        for (int k = 0; k < QPK; k++) s_m[k][w] = mloc[k];
    __syncthreads();
    if (tid < QPK) {
        float m = s_m[tid][0];
#pragma unroll
        for (int i = 1; i < 8; i++) m = fmaxf(m, s_m[tid][i]);
        s_mf[tid] = m;
    }
    __syncthreads();

    float lsum[QPK];
#pragma unroll
    for (int k = 0; k < QPK; k++) {
        float e = (tid < ntok) ? __expf(lg[k] - s_mf[k]) : 0.f;
        if (tid < PART) s_logits[k][tid] = e;
        lsum[k] = e;
    }
#pragma unroll
    for (int off = 16; off; off >>= 1)
#pragma unroll
        for (int k = 0; k < QPK; k++)
            lsum[k] += __shfl_xor_sync(0xffffffffu, lsum[k], off);
    if (lane == 0)
#pragma unroll
        for (int k = 0; k < QPK; k++) s_lred[k][w] = lsum[k];
    __syncthreads();

    if (tid < QPK) {
        float l = 0.f;
#pragma unroll
        for (int i = 0; i < 8; i++) l += s_lred[tid][i];
        int pid = ((n*KVH + h)*QPK + tid)*NPARTS + p;
        g_pm[pid] = s_mf[tid];
        g_pl[pid] = l;
    }

    // ---- Phase 2: V accumulation, statically unrolled over all 8 blocks ----
    int s4 = tid & 3;
    int db = tid >> 2;                  // 0..63
    float acc[QPK][2];
#pragma unroll
    for (int k = 0; k < QPK; k++) acc[k][0] = acc[k][1] = 0.f;

#pragma unroll
    for (int b = 0; b < NBLK; b += 2) {
        const float* vbA = vc + ((size_t)s_bt[b  ]*KVH + h)*(HS*BS);
        const float* vbB = vc + ((size_t)s_bt[b+1]*KVH + h)*(HS*BS);
        float4 vA0 = __ldcs((const float4*)(vbA + db*BS + s4*4));
        float4 vA1 = __ldcs((const float4*)(vbA + (db + 64)*BS + s4*4));
        float4 vB0 = __ldcs((const float4*)(vbB + db*BS + s4*4));
        float4 vB1 = __ldcs((const float4*)(vbB + (db + 64)*BS + s4*4));
#pragma unroll
        for (int k = 0; k < QPK; k++) {
            float4 wA = *(const float4*)&s_logits[k][b*16 + s4*4];
            float4 wB = *(const float4*)&s_logits[k][(b+1)*16 + s4*4];
            acc[k][0] += wA.x*vA0.x + wA.y*vA0.y + wA.z*vA0.z + wA.w*vA0.w;
            acc[k][1] += wA.x*vA1.x + wA.y*vA1.y + wA.z*vA1.z + wA.w*vA1.w;
            acc[k][0] += wB.x*vB0.x + wB.y*vB0.y + wB.z*vB0.z + wB.w*vB0.w;
            acc[k][1] += wB.x*vB1.x + wB.y*vB1.y + wB.z*vB1.z + wB.w*vB1.w;
        }
    }

    // Correct the new token: replace stale cached V with v_new contribution.
    int tl = L - 1;
    if (tl >= start && tl < start + ntok && ((tl & 15) >> 2) == s4) {
        int blk = s_bt[(tl - start) >> 4];
        int s   = tl & 15;
        const float* vbase = vc + ((size_t)blk*KVH + h)*(HS*BS);
        float vst0 = vbase[db*BS + s];
        float vst1 = vbase[(db + 64)*BS + s];
        float vn0  = vnew[((size_t)n*KVH + h)*HS + db];
        float vn1  = vnew[((size_t)n*KVH + h)*HS + db + 64];
        float dd0 = vn0 - vst0, dd1 = vn1 - vst1;
#pragma unroll
        for (int k = 0; k < QPK; k++) {
            float wv = s_logits[k][tl - start];
            acc[k][0] += wv * dd0;
            acc[k][1] += wv * dd1;
        }
    }

    // Combine the 4 s-quarters (lane bits 0..1)
#pragma unroll
    for (int k = 0; k < QPK; k++) {
#pragma unroll
        for (int j = 0; j < 2; j++) {
            acc[k][j] += __shfl_xor_sync(0xffffffffu, acc[k][j], 1);
            acc[k][j] += __shfl_xor_sync(0xffffffffu, acc[k][j], 2);
        }
    }
    if (s4 == 0) {
#pragma unroll
        for (int k = 0; k < QPK; k++) {
            size_t pid = (size_t)((n*KVH + h)*QPK + k)*NPARTS + p;
            g_pout[pid*HS + db]      = acc[k][0];
            g_pout[pid*HS + db + 64] = acc[k][1];
        }
    }

    // ---- Tail: last-arriving CTA of the (n,h) group does the combine ----
    __threadfence();                     // publish this CTA's partials GPU-wide
    __syncthreads();
    if (tid == 0) {
        int v = atomicAdd(&g_cnt[n*KVH + h], 1);
        s_last = (v == np - 1);
    }
    __syncthreads();
    if (!s_last) return;

    if (tid == 0) g_cnt[n*KVH + h] = 0;  // reset counter for the next launch
    __threadfence();                     // acquire other CTAs' published writes

    // 256 threads cover 4 heads x 128 dims (2 dims each)
    int k  = tid >> 6;                   // q-head 0..3
    int dd = tid & 63;                   // dim base 0..63 (also dd+64)
    int gbase = ((n*KVH + h)*QPK + k)*NPARTS;

    float m = -FLT_MAX;
    for (int pp = 0; pp < np; pp++) m = fmaxf(m, g_pm[gbase + pp]);
    float l = 0.f, o0 = 0.f, o1 = 0.f;
    for (int pp = 0; pp < np; pp++) {
        float a = __expf(g_pm[gbase + pp] - m);
        l  += a * g_pl[gbase + pp];
        o0 += a * g_pout[(size_t)(gbase + pp)*HS + dd];
        o1 += a * g_pout[(size_t)(gbase + pp)*HS + dd + 64];
    }
    float inv = 1.f / l;
    out[((size_t)n*NH + h*QPK + k)*HS + dd]      = o0 * inv;
    out[((size_t)n*NH + h*QPK + k)*HS + dd + 64] = o1 * inv;
}

extern "C" void kernel_launch(void* const* d_in, const int* in_sizes, int n_in,
                              void* d_out, int out_size)
{
    const float* q   = (const float*)d_in[0];
    const float* k   = (const float*)d_in[1];
    const float* v   = (const float*)d_in[2];
    const float* kc  = (const float*)d_in[3];
    const float* vc  = (const float*)d_in[4];
    const int*   bt  = (const int*)d_in[5];
    const int*   ctx = (const int*)d_in[6];

    dim3 g1(KVH, NPARTS, NS);
    attn_fused<<<g1, 256>>>(q, k, v, kc, vc, bt, ctx, (float*)d_out);
}